// round 16
// baseline (speedup 1.0000x reference)
#include <cuda_runtime.h>
#include <cstdint>

#define NN   50000
#define NP   50048            // padded rows = 391 * 128
#define EE   800000
#define INF  512
#define HF   128
#define OF   64
#define GBLK 391              // ceil(50000/128)
#define LOB  196              // lo-half tiles
#define HIB  195              // hi-half tiles
#define LON  (LOB * 128)      // 25088 nodes in lo half
#define SCB  196              // scan blocks

// ---------------- scratch (static device globals) ----------------------------
__device__ float g_WAT [(size_t)NN * HF];
__device__ float g_cat [(size_t)NP * 2 * HF];  // (xA | xX), pre-rounded
__device__ float g_t   [(size_t)NP * HF];
__device__ float g_WXr [HF * INF];
__device__ float g_Wr  [HF * 2 * HF];
__device__ float g_Wf1r[HF * HF];
__device__ float g_Wf2p[OF * HF];
__device__ float g_bf2p[OF];
__device__ int   g_hist[NN];                   // self-cleaned by k_scanA
__device__ int   g_off [NN + 1];
__device__ int   g_cur [NN];
__device__ int   g_dst [EE];
__device__ int   g_bsum[SCB];
__device__ int   g_boff[SCB];
__device__ int   g_rmin = 0x7fffffff;          // reset by k_fold
__device__ float g_sum  [HF];                  // zeroed by k_fold
__device__ float g_sumsq[HF];

// ---------------- helpers ----------------------------------------------------
__device__ __forceinline__ float rna(float f) {
    float r; asm("cvt.rna.tf32.f32 %0, %1;" : "=f"(r) : "f"(f)); return r;
}
__device__ __forceinline__ uint32_t rnau(float f) { return __float_as_uint(rna(f)); }
__device__ __forceinline__ uint32_t s2u(const void* p) {
    uint32_t a;
    asm("{ .reg .u64 t; cvta.to.shared.u64 t, %1; cvt.u32.u64 %0, t; }" : "=r"(a) : "l"(p));
    return a;
}
__device__ __forceinline__ void cp16(uint32_t d, const void* s) {
    asm volatile("cp.async.cg.shared.global [%0], [%1], 16;" :: "r"(d), "l"(s));
}
__device__ __forceinline__ void cp16z(uint32_t d, const void* s, int sz) {
    asm volatile("cp.async.cg.shared.global [%0], [%1], 16, %2;" :: "r"(d), "l"(s), "r"(sz));
}
#define MMA_TF32(acc, af, bf)                                                 \
    asm volatile(                                                             \
        "mma.sync.aligned.m16n8k8.row.col.f32.tf32.tf32.f32 "                 \
        "{%0,%1,%2,%3},{%4,%5,%6,%7},{%8,%9},{%0,%1,%2,%3};"                  \
        : "+f"((acc)[0]), "+f"((acc)[1]), "+f"((acc)[2]), "+f"((acc)[3])      \
        : "r"((af)[0]), "r"((af)[1]), "r"((af)[2]), "r"((af)[3]),             \
          "r"((bf)[0]), "r"((bf)[1]))

// ---------------- round weights (side stream) --------------------------------
__global__ void k_roundw(const float* __restrict__ WX, const float* __restrict__ W,
                         const float* __restrict__ Wf1) {
    int i = blockIdx.x * blockDim.x + threadIdx.x;
    if (i < HF * INF)    g_WXr[i]  = rna(WX[i]);
    if (i < HF * 2 * HF) g_Wr[i]   = rna(W[i]);
    if (i < HF * HF)     g_Wf1r[i] = rna(Wf1[i]);
}

// ---------------- histogram + row min (8 edges / thread) ---------------------
__global__ void k_hist(const int* __restrict__ row, int E) {
    int base = (blockIdx.x * blockDim.x + threadIdx.x) * 8;
    int rmn = 0x7fffffff;
    int r[8]; bool ok[8];
    #pragma unroll
    for (int u = 0; u < 8; ++u) {
        int e = base + u;
        ok[u] = e < E;
        if (ok[u]) { r[u] = row[e]; rmn = min(rmn, r[u]); }
    }
    #pragma unroll
    for (int u = 0; u < 8; ++u)
        if (ok[u]) atomicAdd(&g_hist[r[u]], 1);
    unsigned wm = __reduce_min_sync(0xffffffffu, (unsigned)rmn);
    if ((threadIdx.x & 31) == 0) atomicMin(&g_rmin, (int)wm);
}

// ---------------- parallel 3-phase exclusive scan (self-cleans g_hist) -------
__global__ void k_scanA() {
    __shared__ int s[256];
    int tid = threadIdx.x;
    int i = blockIdx.x * 256 + tid;
    int v = (i < NN) ? g_hist[i] : 0;
    if (i < NN) g_hist[i] = 0;                  // self-clean for next replay
    s[tid] = v;
    __syncthreads();
    #pragma unroll
    for (int ofs = 1; ofs < 256; ofs <<= 1) {
        int t = (tid >= ofs) ? s[tid - ofs] : 0;
        __syncthreads();
        s[tid] += t;
        __syncthreads();
    }
    if (i < NN) g_off[i] = s[tid] - v;
    if (tid == 255) g_bsum[blockIdx.x] = s[255];
}
__global__ void k_scanB() {
    __shared__ int s[256];
    int tid = threadIdx.x;
    int v = (tid < SCB) ? g_bsum[tid] : 0;
    s[tid] = v;
    __syncthreads();
    #pragma unroll
    for (int ofs = 1; ofs < 256; ofs <<= 1) {
        int t = (tid >= ofs) ? s[tid - ofs] : 0;
        __syncthreads();
        s[tid] += t;
        __syncthreads();
    }
    if (tid < SCB) g_boff[tid] = s[tid] - v;
}
__global__ void k_scanC(int E) {
    int i = blockIdx.x * 256 + threadIdx.x;
    if (i < NN) {
        int o = g_off[i] + g_boff[blockIdx.x];
        g_off[i] = o;
        g_cur[i] = o;
    }
    if (i == 0) g_off[NN] = E;
}

// ---------------- bin edges by row (8 edges / thread) ------------------------
__global__ void k_bin(const int* __restrict__ row, const int* __restrict__ col, int E) {
    int base = (blockIdx.x * blockDim.x + threadIdx.x) * 8;
    int r[8], c[8], p[8];
    bool ok[8];
    #pragma unroll
    for (int u = 0; u < 8; ++u) {
        int e = base + u;
        ok[u] = e < E;
        if (ok[u]) { r[u] = row[e]; c[u] = col[e]; }
    }
    #pragma unroll
    for (int u = 0; u < 8; ++u)
        if (ok[u]) p[u] = atomicAdd(&g_cur[r[u]], 1);
    #pragma unroll
    for (int u = 0; u < 8; ++u)
        if (ok[u]) g_dst[p[u]] = c[u];
}

// ---------------- transpose WA [H,N] -> WAT [N,H] ----------------------------
__global__ void k_transpose(const float* __restrict__ WA) {
    __shared__ float tile[32][33];
    int n0 = blockIdx.x * 32, h0 = blockIdx.y * 32;
    int tx = threadIdx.x, ty = threadIdx.y;
    #pragma unroll
    for (int j = 0; j < 32; j += 8) {
        int h = h0 + ty + j, n = n0 + tx;
        tile[ty + j][tx] = (n < NN) ? WA[(size_t)h * NN + n] : 0.f;
    }
    __syncthreads();
    #pragma unroll
    for (int j = 0; j < 32; j += 8) {
        int n = n0 + ty + j, h = h0 + tx;
        if (n < NN) g_WAT[(size_t)n * HF + h] = tile[tx][ty + j];
    }
}

// ---------------- gather (node-range parameterized) --------------------------
__global__ void k_gather(const float* __restrict__ bA, int w0, int nNodes) {
    int id   = (blockIdx.x * blockDim.x + threadIdx.x) >> 5;
    int lane = threadIdx.x & 31;
    if (id >= nNodes) return;
    int w = w0 + id;
    int bkt = w + g_rmin;
    int s = 0, e = 0;
    if (bkt < NN) { s = g_off[bkt]; e = g_off[bkt + 1]; }
    float4 acc = *(const float4*)(bA + lane * 4);
    int j = s;
    for (; j + 8 <= e; j += 8) {
        int cc[8];
        #pragma unroll
        for (int u = 0; u < 8; ++u) cc[u] = g_dst[j + u];
        float4 v[8];
        #pragma unroll
        for (int u = 0; u < 8; ++u)
            v[u] = *(const float4*)(g_WAT + (size_t)cc[u] * HF + lane * 4);
        float4 p0, p1, p2, p3;
        p0.x = v[0].x + v[1].x; p0.y = v[0].y + v[1].y; p0.z = v[0].z + v[1].z; p0.w = v[0].w + v[1].w;
        p1.x = v[2].x + v[3].x; p1.y = v[2].y + v[3].y; p1.z = v[2].z + v[3].z; p1.w = v[2].w + v[3].w;
        p2.x = v[4].x + v[5].x; p2.y = v[4].y + v[5].y; p2.z = v[4].z + v[5].z; p2.w = v[4].w + v[5].w;
        p3.x = v[6].x + v[7].x; p3.y = v[6].y + v[7].y; p3.z = v[6].z + v[7].z; p3.w = v[6].w + v[7].w;
        p0.x += p1.x; p0.y += p1.y; p0.z += p1.z; p0.w += p1.w;
        p2.x += p3.x; p2.y += p3.y; p2.z += p3.z; p2.w += p3.w;
        acc.x += p0.x + p2.x; acc.y += p0.y + p2.y;
        acc.z += p0.z + p2.z; acc.w += p0.w + p2.w;
    }
    for (; j < e; ++j) {
        int c = g_dst[j];
        float4 v = *(const float4*)(g_WAT + (size_t)c * HF + lane * 4);
        acc.x += v.x; acc.y += v.y; acc.z += v.z; acc.w += v.w;
    }
    acc.x = rna(acc.x); acc.y = rna(acc.y); acc.z = rna(acc.z); acc.w = rna(acc.w);
    *((float4*)(g_cat + (size_t)w * (2 * HF) + lane * 4)) = acc;
}

// ---------------- tf32 mma.sync GEMM (2-stage, block-offset) -----------------
template<int BN, int EPI, int GUARD, int RNDA, int RNDS>
__global__ __launch_bounds__(256)
void k_mm(const float* __restrict__ A, int lda,
          const float* __restrict__ B,
          const float* __restrict__ bias,
          float* __restrict__ C, int ldc, int K, int boff)
{
    constexpr int BM = 128, BK = 16, STR = 20;
    constexpr int WXn = 4, WTN = BN / WXn;
    constexpr int NF = WTN / 8;
    constexpr int MF = 4;
    __shared__ __align__(16) float As[2][BM * STR];
    __shared__ __align__(16) float Bs[2][BN * STR];

    const int tid  = threadIdx.x;
    const int lane = tid & 31, warp = tid >> 5;
    const int wy = warp / WXn, wx = warp % WXn;
    const int g = lane >> 2, tg = lane & 3;
    const int bm = (blockIdx.x + boff) * BM;

    float acc[MF][NF][4];
    #pragma unroll
    for (int i = 0; i < MF; ++i)
        #pragma unroll
        for (int j = 0; j < NF; ++j)
            #pragma unroll
            for (int c = 0; c < 4; ++c) acc[i][j][c] = 0.f;

    const uint32_t aS = s2u(As), bS = s2u(Bs);
    const int T = K / BK;

    auto load_tiles = [&](int t, int st) {
        const int k0 = t * BK;
        #pragma unroll
        for (int i = 0; i < BM * 4 / 256; ++i) {
            int idx = tid + i * 256;
            int r = idx >> 2, ch = idx & 3;
            uint32_t d = aS + (uint32_t)(st * BM * STR + r * STR + ch * 4) * 4;
            if (GUARD) {
                bool v = (bm + r) < NN;
                cp16z(d, A + (v ? ((size_t)(bm + r) * lda + k0 + ch * 4) : 0), v ? 16 : 0);
            } else {
                cp16(d, A + (size_t)(bm + r) * lda + k0 + ch * 4);
            }
        }
        #pragma unroll
        for (int i = 0; i < BN * 4 / 256; ++i) {
            int idx = tid + i * 256;
            int r = idx >> 2, ch = idx & 3;
            cp16(bS + (uint32_t)(st * BN * STR + r * STR + ch * 4) * 4,
                 B + (size_t)r * K + k0 + ch * 4);
        }
        asm volatile("cp.async.commit_group;");
    };

    load_tiles(0, 0);

    for (int t = 0; t < T; ++t) {
        const int cur = t & 1;
        if (t + 1 < T) {
            load_tiles(t + 1, cur ^ 1);
            asm volatile("cp.async.wait_group 1;");
        } else {
            asm volatile("cp.async.wait_group 0;");
        }
        __syncthreads();

        const float* as = As[cur];
        const float* bs = Bs[cur];
        #pragma unroll
        for (int ks = 0; ks < 2; ++ks) {
            uint32_t af[MF][4], bf[NF][2];
            #pragma unroll
            for (int mf = 0; mf < MF; ++mf) {
                int r0 = (wy * 64 + mf * 16 + g) * STR + ks * 8 + tg;
                if (RNDA) {
                    af[mf][0] = rnau(as[r0]);
                    af[mf][1] = rnau(as[r0 + 8 * STR]);
                    af[mf][2] = rnau(as[r0 + 4]);
                    af[mf][3] = rnau(as[r0 + 8 * STR + 4]);
                } else {
                    af[mf][0] = __float_as_uint(as[r0]);
                    af[mf][1] = __float_as_uint(as[r0 + 8 * STR]);
                    af[mf][2] = __float_as_uint(as[r0 + 4]);
                    af[mf][3] = __float_as_uint(as[r0 + 8 * STR + 4]);
                }
            }
            #pragma unroll
            for (int nf = 0; nf < NF; ++nf) {
                int rb = (wx * WTN + nf * 8 + g) * STR + ks * 8 + tg;
                bf[nf][0] = __float_as_uint(bs[rb]);
                bf[nf][1] = __float_as_uint(bs[rb + 4]);
            }
            #pragma unroll
            for (int mf = 0; mf < MF; ++mf)
                #pragma unroll
                for (int nf = 0; nf < NF; ++nf)
                    MMA_TF32(acc[mf][nf], af[mf], bf[nf]);
        }
        __syncthreads();
    }

    #pragma unroll
    for (int nf = 0; nf < NF; ++nf) {
        int n0 = wx * WTN + nf * 8 + tg * 2;
        float b0 = bias[n0], b1 = bias[n0 + 1];
        #pragma unroll
        for (int mf = 0; mf < MF; ++mf) {
            #pragma unroll
            for (int half = 0; half < 2; ++half) {
                int m = bm + wy * 64 + mf * 16 + g + half * 8;
                if (m >= NN) continue;
                float v0 = acc[mf][nf][half * 2 + 0] + b0;
                float v1 = acc[mf][nf][half * 2 + 1] + b1;
                if (EPI == 2) { v0 = fmaxf(v0, 0.f); v1 = fmaxf(v1, 0.f); }
                if (RNDS) { v0 = rna(v0); v1 = rna(v1); }
                *(float2*)(C + (size_t)m * ldc + n0) = make_float2(v0, v1);
            }
        }
    }
}

// ---------------- fused GEMM2+GEMM3 (dynamic smem, block-offset) -------------
#define MM23_AS     0
#define MM23_BS     (2 * 128 * 20)
#define MM23_H1     (4 * 128 * 20)
#define MM23_FLOATS (MM23_H1 + 128 * 132)
#define MM23_BYTES  (MM23_FLOATS * 4)

__global__ __launch_bounds__(256)
void k_mm23(const float* __restrict__ bW, const float* __restrict__ bf1, int boff)
{
    constexpr int BM = 128, BK = 16, STR = 20, STR2 = 132;
    constexpr int WXn = 4, WTN = 32, NF = 4, MF = 4;
    extern __shared__ float dyn[];
    float* As  = dyn + MM23_AS;
    float* Bs  = dyn + MM23_BS;
    float* h1s = dyn + MM23_H1;
    __shared__ float s_sum[HF], s_sq[HF];

    const int tid  = threadIdx.x;
    const int lane = tid & 31, warp = tid >> 5;
    const int wy = warp / WXn, wx = warp % WXn;
    const int g = lane >> 2, tg = lane & 3;
    const int bm = (blockIdx.x + boff) * BM;
    const float* cat = g_cat;
    const float* W   = g_Wr;
    const float* Wf1 = g_Wf1r;

    if (tid < HF) { s_sum[tid] = 0.f; s_sq[tid] = 0.f; }

    float acc[MF][NF][4];
    #pragma unroll
    for (int i = 0; i < MF; ++i)
        #pragma unroll
        for (int j = 0; j < NF; ++j)
            #pragma unroll
            for (int c = 0; c < 4; ++c) acc[i][j][c] = 0.f;

    const uint32_t aS = s2u(As), bS = s2u(Bs);

    auto loadB = [&](int t, int st) {
        const int k0 = t * BK;
        #pragma unroll
        for (int i = 0; i < 2; ++i) {
            int idx = tid + i * 256;
            int r = idx >> 2, ch = idx & 3;
            cp16(aS + (uint32_t)(st * BM * STR + r * STR + ch * 4) * 4,
                 cat + (size_t)(bm + r) * 256 + k0 + ch * 4);
        }
        #pragma unroll
        for (int i = 0; i < 2; ++i) {
            int idx = tid + i * 256;
            int r = idx >> 2, ch = idx & 3;
            cp16(bS + (uint32_t)(st * HF * STR + r * STR + ch * 4) * 4,
                 W + (size_t)r * 256 + k0 + ch * 4);
        }
        asm volatile("cp.async.commit_group;");
    };

    loadB(0, 0);
    for (int t = 0; t < 16; ++t) {
        const int cur = t & 1;
        if (t + 1 < 16) {
            loadB(t + 1, cur ^ 1);
            asm volatile("cp.async.wait_group 1;");
        } else {
            asm volatile("cp.async.wait_group 0;");
        }
        __syncthreads();
        const float* as = As + cur * BM * STR;
        const float* bs = Bs + cur * HF * STR;
        #pragma unroll
        for (int ks = 0; ks < 2; ++ks) {
            uint32_t af[MF][4], bf[NF][2];
            #pragma unroll
            for (int mf = 0; mf < MF; ++mf) {
                int r0 = (wy * 64 + mf * 16 + g) * STR + ks * 8 + tg;
                af[mf][0] = __float_as_uint(as[r0]);
                af[mf][1] = __float_as_uint(as[r0 + 8 * STR]);
                af[mf][2] = __float_as_uint(as[r0 + 4]);
                af[mf][3] = __float_as_uint(as[r0 + 8 * STR + 4]);
            }
            #pragma unroll
            for (int nf = 0; nf < NF; ++nf) {
                int rb = (wx * WTN + nf * 8 + g) * STR + ks * 8 + tg;
                bf[nf][0] = __float_as_uint(bs[rb]);
                bf[nf][1] = __float_as_uint(bs[rb + 4]);
            }
            #pragma unroll
            for (int mf = 0; mf < MF; ++mf)
                #pragma unroll
                for (int nf = 0; nf < NF; ++nf)
                    MMA_TF32(acc[mf][nf], af[mf], bf[nf]);
        }
        __syncthreads();
    }

    // prefetch stage-C B tile 0 (Wf1)
    {
        #pragma unroll
        for (int i = 0; i < 2; ++i) {
            int idx = tid + i * 256;
            int r = idx >> 2, ch = idx & 3;
            cp16(bS + (uint32_t)(r * STR + ch * 4) * 4,
                 Wf1 + (size_t)r * HF + ch * 4);
        }
        asm volatile("cp.async.commit_group;");
    }

    // stage-B epilogue: skip + relu + rna -> h1s
    #pragma unroll
    for (int nf = 0; nf < NF; ++nf) {
        int n0 = wx * WTN + nf * 8 + tg * 2;
        float b0 = bW[n0], b1 = bW[n0 + 1];
        #pragma unroll
        for (int mf = 0; mf < MF; ++mf) {
            #pragma unroll
            for (int half = 0; half < 2; ++half) {
                int ml = wy * 64 + mf * 16 + g + half * 8;
                const float* sp = cat + (size_t)(bm + ml) * 256;
                float v0 = acc[mf][nf][half * 2 + 0] + b0 + sp[n0]     + sp[128 + n0];
                float v1 = acc[mf][nf][half * 2 + 1] + b1 + sp[n0 + 1] + sp[128 + n0 + 1];
                v0 = rna(fmaxf(v0, 0.f)); v1 = rna(fmaxf(v1, 0.f));
                *(float2*)(h1s + ml * STR2 + n0) = make_float2(v0, v1);
                acc[mf][nf][half * 2 + 0] = 0.f;
                acc[mf][nf][half * 2 + 1] = 0.f;
            }
        }
    }
    __syncthreads();

    // stage C: K = 128, A from h1s, B = Wf1
    auto loadC = [&](int t, int st) {
        const int k0 = t * BK;
        #pragma unroll
        for (int i = 0; i < 2; ++i) {
            int idx = tid + i * 256;
            int r = idx >> 2, ch = idx & 3;
            cp16(bS + (uint32_t)(st * HF * STR + r * STR + ch * 4) * 4,
                 Wf1 + (size_t)r * HF + k0 + ch * 4);
        }
        asm volatile("cp.async.commit_group;");
    };

    for (int t = 0; t < 8; ++t) {
        const int cur = t & 1;
        if (t + 1 < 8) {
            loadC(t + 1, cur ^ 1);
            asm volatile("cp.async.wait_group 1;");
        } else {
            asm volatile("cp.async.wait_group 0;");
        }
        __syncthreads();
        const float* bs = Bs + cur * HF * STR;
        const int kb = t * BK;
        #pragma unroll
        for (int ks = 0; ks < 2; ++ks) {
            uint32_t af[MF][4], bf[NF][2];
            #pragma unroll
            for (int mf = 0; mf < MF; ++mf) {
                int r0 = (wy * 64 + mf * 16 + g) * STR2 + kb + ks * 8 + tg;
                af[mf][0] = __float_as_uint(h1s[r0]);
                af[mf][1] = __float_as_uint(h1s[r0 + 8 * STR2]);
                af[mf][2] = __float_as_uint(h1s[r0 + 4]);
                af[mf][3] = __float_as_uint(h1s[r0 + 8 * STR2 + 4]);
            }
            #pragma unroll
            for (int nf = 0; nf < NF; ++nf) {
                int rb = (wx * WTN + nf * 8 + g) * STR + ks * 8 + tg;
                bf[nf][0] = __float_as_uint(bs[rb]);
                bf[nf][1] = __float_as_uint(bs[rb + 4]);
            }
            #pragma unroll
            for (int mf = 0; mf < MF; ++mf)
                #pragma unroll
                for (int nf = 0; nf < NF; ++nf)
                    MMA_TF32(acc[mf][nf], af[mf], bf[nf]);
        }
        __syncthreads();
    }

    // stage-C epilogue: relu; stats on unrounded; store rounded g_t
    #pragma unroll
    for (int nf = 0; nf < NF; ++nf) {
        int n0 = wx * WTN + nf * 8 + tg * 2;
        float b0 = bf1[n0], b1 = bf1[n0 + 1];
        float ps0 = 0.f, pq0 = 0.f, ps1 = 0.f, pq1 = 0.f;
        #pragma unroll
        for (int mf = 0; mf < MF; ++mf) {
            #pragma unroll
            for (int half = 0; half < 2; ++half) {
                int m = bm + wy * 64 + mf * 16 + g + half * 8;
                if (m >= NN) continue;
                float v0 = fmaxf(acc[mf][nf][half * 2 + 0] + b0, 0.f);
                float v1 = fmaxf(acc[mf][nf][half * 2 + 1] + b1, 0.f);
                ps0 += v0; pq0 += v0 * v0; ps1 += v1; pq1 += v1 * v1;
                *(float2*)(g_t + (size_t)m * HF + n0) = make_float2(rna(v0), rna(v1));
            }
        }
        #pragma unroll
        for (int msk = 16; msk >= 4; msk >>= 1) {
            ps0 += __shfl_xor_sync(0xffffffffu, ps0, msk);
            pq0 += __shfl_xor_sync(0xffffffffu, pq0, msk);
            ps1 += __shfl_xor_sync(0xffffffffu, ps1, msk);
            pq1 += __shfl_xor_sync(0xffffffffu, pq1, msk);
        }
        if (g == 0) {
            atomicAdd(&s_sum[n0],     ps0); atomicAdd(&s_sq[n0],     pq0);
            atomicAdd(&s_sum[n0 + 1], ps1); atomicAdd(&s_sq[n0 + 1], pq1);
        }
    }
    __syncthreads();
    if (tid < HF) {
        atomicAdd(&g_sum[tid],   s_sum[tid]);
        atomicAdd(&g_sumsq[tid], s_sq[tid]);
    }
}

// ---------------- fold BN into Wf2/bf2; self-clean stats + rmin --------------
__global__ void k_fold(const float* __restrict__ gamma, const float* __restrict__ beta,
                       const float* __restrict__ Wf2,   const float* __restrict__ bf2,
                       int M) {
    __shared__ float a[HF], b[HF];
    int t = threadIdx.x;
    if (t < HF) {
        float inv  = 1.f / (float)M;
        float mean = g_sum[t] * inv;
        float var  = g_sumsq[t] * inv - mean * mean;
        float av   = gamma[t] * rsqrtf(var + 1e-5f);
        a[t] = av;
        b[t] = beta[t] - mean * av;
        g_sum[t] = 0.f;                         // self-clean for next replay
        g_sumsq[t] = 0.f;
    }
    if (t == 0) g_rmin = 0x7fffffff;            // self-clean
    __syncthreads();
    for (int i = t; i < OF * HF; i += blockDim.x)
        g_Wf2p[i] = rna(Wf2[i] * a[i & (HF - 1)]);
    if (t < OF) {
        float s = bf2[t];
        for (int h = 0; h < HF; ++h) s += b[h] * Wf2[t * HF + h];
        g_bf2p[t] = s;
    }
}

// -----------------------------------------------------------------------------
extern "C" void kernel_launch(void* const* d_in, const int* in_sizes, int n_in,
                              void* d_out, int out_size) {
    const float* x     = (const float*)d_in[0];
    const int*   ei    = (const int*)  d_in[1];
    const float* WA    = (const float*)d_in[2];
    const float* bA    = (const float*)d_in[3];
    const float* WX    = (const float*)d_in[4];
    const float* bX    = (const float*)d_in[5];
    const float* W     = (const float*)d_in[6];
    const float* bW    = (const float*)d_in[7];
    const float* Wf1   = (const float*)d_in[8];
    const float* bf1   = (const float*)d_in[9];
    const float* gamma = (const float*)d_in[10];
    const float* beta  = (const float*)d_in[11];
    const float* Wf2   = (const float*)d_in[12];
    const float* bf2   = (const float*)d_in[13];
    float* out = (float*)d_out;

    const int E = in_sizes[1] / 2;
    const int M = NN;
    const int* row = ei;
    const int* col = ei + E;

    float *pCat, *pT, *pWXr, *pW2, *pB2;
    cudaGetSymbolAddress((void**)&pCat, g_cat);
    cudaGetSymbolAddress((void**)&pT,   g_t);
    cudaGetSymbolAddress((void**)&pWXr, g_WXr);
    cudaGetSymbolAddress((void**)&pW2,  g_Wf2p);
    cudaGetSymbolAddress((void**)&pB2,  g_bf2p);

    static int inited = 0;
    static cudaStream_t sE, sT, sG;
    static cudaEvent_t evRoot, evT, evA1, evA2, evG1, evG2;
    if (!inited) {
        cudaFuncSetAttribute(k_mm23, cudaFuncAttributeMaxDynamicSharedMemorySize,
                             MM23_BYTES);
        cudaStreamCreateWithFlags(&sE, cudaStreamNonBlocking);
        cudaStreamCreateWithFlags(&sT, cudaStreamNonBlocking);
        cudaStreamCreateWithFlags(&sG, cudaStreamNonBlocking);
        cudaEventCreateWithFlags(&evRoot, cudaEventDisableTiming);
        cudaEventCreateWithFlags(&evT,    cudaEventDisableTiming);
        cudaEventCreateWithFlags(&evA1,   cudaEventDisableTiming);
        cudaEventCreateWithFlags(&evA2,   cudaEventDisableTiming);
        cudaEventCreateWithFlags(&evG1,   cudaEventDisableTiming);
        cudaEventCreateWithFlags(&evG2,   cudaEventDisableTiming);
        inited = 1;
    }

    // ---- fork -----------------------------------------------------------------
    cudaEventRecord(evRoot, 0);
    cudaStreamWaitEvent(sE, evRoot, 0);
    cudaStreamWaitEvent(sT, evRoot, 0);
    cudaStreamWaitEvent(sG, evRoot, 0);

    // stream sT: transpose WA
    k_transpose<<<dim3((NN + 31) / 32, HF / 32), dim3(32, 8), 0, sT>>>(WA);
    cudaEventRecord(evT, sT);

    // stream sG: round weights, then GEMM1 in lo/hi halves
    k_roundw<<<(HF * INF + 255) / 256, 256, 0, sG>>>(WX, W, Wf1);
    k_mm<128, 0, 1, 1, 1><<<LOB, 256, 0, sG>>>(x, INF, pWXr, bX, pCat + HF, 2 * HF, INF, 0);
    cudaEventRecord(evG1, sG);
    k_mm<128, 0, 1, 1, 1><<<HIB, 256, 0, sG>>>(x, INF, pWXr, bX, pCat + HF, 2 * HF, INF, LOB);
    cudaEventRecord(evG2, sG);

    // stream sE: edge pipeline, then gather in lo/hi halves
    k_hist<<<(E / 8 + 255) / 256, 256, 0, sE>>>(row, E);
    k_scanA<<<SCB, 256, 0, sE>>>();
    k_scanB<<<1, 256, 0, sE>>>();
    k_scanC<<<SCB, 256, 0, sE>>>(E);
    k_bin<<<(E / 8 + 255) / 256, 256, 0, sE>>>(row, col, E);
    cudaStreamWaitEvent(sE, evT, 0);
    k_gather<<<(LON * 32 + 255) / 256, 256, 0, sE>>>(bA, 0, LON);
    cudaEventRecord(evA1, sE);
    k_gather<<<((NN - LON) * 32 + 255) / 256, 256, 0, sE>>>(bA, LON, NN - LON);
    cudaEventRecord(evA2, sE);

    // stream 0: mm23 lo (overlaps gather_hi / gemm1_hi), then mm23 hi
    cudaStreamWaitEvent(0, evA1, 0);
    cudaStreamWaitEvent(0, evG1, 0);
    k_mm23<<<LOB, 256, MM23_BYTES>>>(bW, bf1, 0);
    cudaStreamWaitEvent(0, evA2, 0);
    cudaStreamWaitEvent(0, evG2, 0);
    k_mm23<<<HIB, 256, MM23_BYTES>>>(bW, bf1, LOB);

    // fold BN, final GEMM
    k_fold<<<1, 256>>>(gamma, beta, Wf2, bf2, M);
    k_mm<64, 0, 0, 0, 0><<<GBLK, 256>>>(pT, HF, pW2, pB2, out, OF, HF, 0);
}

// round 17
// speedup vs baseline: 1.5689x; 1.5689x over previous
#include <cuda_runtime.h>
#include <cstdint>

#define NN   50000
#define NP   50048            // padded rows = 391 * 128
#define EE   800000
#define INF  512
#define HF   128
#define OF   64
#define GBLK 391              // ceil(50000/128)
#define SCB  196              // scan blocks

// ---------------- scratch (static device globals) ----------------------------
__device__ float g_WAT [(size_t)NN * HF];
__device__ float g_cat [(size_t)NP * 2 * HF];  // (xA | xX), pre-rounded
__device__ float g_t   [(size_t)NP * HF];
__device__ float g_WXr [HF * INF];
__device__ float g_Wr  [HF * 2 * HF];
__device__ float g_Wf1r[HF * HF];
__device__ float g_Wf2p[OF * HF];
__device__ float g_bf2p[OF];
__device__ int   g_hist[NN];                   // self-cleaned by k_scanA
__device__ int   g_off [NN + 1];
__device__ int   g_cur [NN];
__device__ int   g_dst [EE];
__device__ int   g_bsum[SCB];
__device__ int   g_boff[SCB];
__device__ int   g_rmin = 0x7fffffff;          // reset by k_fold
__device__ float g_sum  [HF];                  // zeroed by k_fold
__device__ float g_sumsq[HF];

// ---------------- helpers ----------------------------------------------------
__device__ __forceinline__ float rna(float f) {
    float r; asm("cvt.rna.tf32.f32 %0, %1;" : "=f"(r) : "f"(f)); return r;
}
__device__ __forceinline__ uint32_t rnau(float f) { return __float_as_uint(rna(f)); }
__device__ __forceinline__ uint32_t s2u(const void* p) {
    uint32_t a;
    asm("{ .reg .u64 t; cvta.to.shared.u64 t, %1; cvt.u32.u64 %0, t; }" : "=r"(a) : "l"(p));
    return a;
}
__device__ __forceinline__ void cp16(uint32_t d, const void* s) {
    asm volatile("cp.async.cg.shared.global [%0], [%1], 16;" :: "r"(d), "l"(s));
}
__device__ __forceinline__ void cp16z(uint32_t d, const void* s, int sz) {
    asm volatile("cp.async.cg.shared.global [%0], [%1], 16, %2;" :: "r"(d), "l"(s), "r"(sz));
}
#define MMA_TF32(acc, af, bf)                                                 \
    asm volatile(                                                             \
        "mma.sync.aligned.m16n8k8.row.col.f32.tf32.tf32.f32 "                 \
        "{%0,%1,%2,%3},{%4,%5,%6,%7},{%8,%9},{%0,%1,%2,%3};"                  \
        : "+f"((acc)[0]), "+f"((acc)[1]), "+f"((acc)[2]), "+f"((acc)[3])      \
        : "r"((af)[0]), "r"((af)[1]), "r"((af)[2]), "r"((af)[3]),             \
          "r"((bf)[0]), "r"((bf)[1]))

// ---------------- round weights (side stream) --------------------------------
__global__ void k_roundw(const float* __restrict__ WX, const float* __restrict__ W,
                         const float* __restrict__ Wf1) {
    int i = blockIdx.x * blockDim.x + threadIdx.x;
    if (i < HF * INF)    g_WXr[i]  = rna(WX[i]);
    if (i < HF * 2 * HF) g_Wr[i]   = rna(W[i]);
    if (i < HF * HF)     g_Wf1r[i] = rna(Wf1[i]);
}

// ---------------- histogram + row min (8 edges / thread) ---------------------
__global__ void k_hist(const int* __restrict__ row, int E) {
    int base = (blockIdx.x * blockDim.x + threadIdx.x) * 8;
    int rmn = 0x7fffffff;
    int r[8]; bool ok[8];
    #pragma unroll
    for (int u = 0; u < 8; ++u) {
        int e = base + u;
        ok[u] = e < E;
        if (ok[u]) { r[u] = row[e]; rmn = min(rmn, r[u]); }
    }
    #pragma unroll
    for (int u = 0; u < 8; ++u)
        if (ok[u]) atomicAdd(&g_hist[r[u]], 1);
    unsigned wm = __reduce_min_sync(0xffffffffu, (unsigned)rmn);
    if ((threadIdx.x & 31) == 0) atomicMin(&g_rmin, (int)wm);
}

// ---------------- parallel 3-phase exclusive scan (self-cleans g_hist) -------
__global__ void k_scanA() {
    __shared__ int s[256];
    int tid = threadIdx.x;
    int i = blockIdx.x * 256 + tid;
    int v = (i < NN) ? g_hist[i] : 0;
    if (i < NN) g_hist[i] = 0;                  // self-clean for next replay
    s[tid] = v;
    __syncthreads();
    #pragma unroll
    for (int ofs = 1; ofs < 256; ofs <<= 1) {
        int t = (tid >= ofs) ? s[tid - ofs] : 0;
        __syncthreads();
        s[tid] += t;
        __syncthreads();
    }
    if (i < NN) g_off[i] = s[tid] - v;
    if (tid == 255) g_bsum[blockIdx.x] = s[255];
}
__global__ void k_scanB() {
    __shared__ int s[256];
    int tid = threadIdx.x;
    int v = (tid < SCB) ? g_bsum[tid] : 0;
    s[tid] = v;
    __syncthreads();
    #pragma unroll
    for (int ofs = 1; ofs < 256; ofs <<= 1) {
        int t = (tid >= ofs) ? s[tid - ofs] : 0;
        __syncthreads();
        s[tid] += t;
        __syncthreads();
    }
    if (tid < SCB) g_boff[tid] = s[tid] - v;
}
__global__ void k_scanC(int E) {
    int i = blockIdx.x * 256 + threadIdx.x;
    if (i < NN) {
        int o = g_off[i] + g_boff[blockIdx.x];
        g_off[i] = o;
        g_cur[i] = o;
    }
    if (i == 0) g_off[NN] = E;
}

// ---------------- bin edges by row (8 edges / thread) ------------------------
__global__ void k_bin(const int* __restrict__ row, const int* __restrict__ col, int E) {
    int base = (blockIdx.x * blockDim.x + threadIdx.x) * 8;
    int r[8], c[8], p[8];
    bool ok[8];
    #pragma unroll
    for (int u = 0; u < 8; ++u) {
        int e = base + u;
        ok[u] = e < E;
        if (ok[u]) { r[u] = row[e]; c[u] = col[e]; }
    }
    #pragma unroll
    for (int u = 0; u < 8; ++u)
        if (ok[u]) p[u] = atomicAdd(&g_cur[r[u]], 1);
    #pragma unroll
    for (int u = 0; u < 8; ++u)
        if (ok[u]) g_dst[p[u]] = c[u];
}

// ---------------- transpose WA [H,N] -> WAT [N,H] ----------------------------
__global__ void k_transpose(const float* __restrict__ WA) {
    __shared__ float tile[32][33];
    int n0 = blockIdx.x * 32, h0 = blockIdx.y * 32;
    int tx = threadIdx.x, ty = threadIdx.y;
    #pragma unroll
    for (int j = 0; j < 32; j += 8) {
        int h = h0 + ty + j, n = n0 + tx;
        tile[ty + j][tx] = (n < NN) ? WA[(size_t)h * NN + n] : 0.f;
    }
    __syncthreads();
    #pragma unroll
    for (int j = 0; j < 32; j += 8) {
        int n = n0 + ty + j, h = h0 + tx;
        if (n < NN) g_WAT[(size_t)n * HF + h] = tile[tx][ty + j];
    }
}

// ---------------- gather xA = segsum(WAT[col]) + bA -> cat[:, :128] ----------
__global__ void k_gather(const float* __restrict__ bA) {
    int w    = (blockIdx.x * blockDim.x + threadIdx.x) >> 5;
    int lane = threadIdx.x & 31;
    if (w >= NN) return;
    int bkt = w + g_rmin;
    int s = 0, e = 0;
    if (bkt < NN) { s = g_off[bkt]; e = g_off[bkt + 1]; }
    float4 acc = *(const float4*)(bA + lane * 4);
    int j = s;
    for (; j + 8 <= e; j += 8) {
        int cc[8];
        #pragma unroll
        for (int u = 0; u < 8; ++u) cc[u] = g_dst[j + u];
        float4 v[8];
        #pragma unroll
        for (int u = 0; u < 8; ++u)
            v[u] = *(const float4*)(g_WAT + (size_t)cc[u] * HF + lane * 4);
        float4 p0, p1, p2, p3;
        p0.x = v[0].x + v[1].x; p0.y = v[0].y + v[1].y; p0.z = v[0].z + v[1].z; p0.w = v[0].w + v[1].w;
        p1.x = v[2].x + v[3].x; p1.y = v[2].y + v[3].y; p1.z = v[2].z + v[3].z; p1.w = v[2].w + v[3].w;
        p2.x = v[4].x + v[5].x; p2.y = v[4].y + v[5].y; p2.z = v[4].z + v[5].z; p2.w = v[4].w + v[5].w;
        p3.x = v[6].x + v[7].x; p3.y = v[6].y + v[7].y; p3.z = v[6].z + v[7].z; p3.w = v[6].w + v[7].w;
        p0.x += p1.x; p0.y += p1.y; p0.z += p1.z; p0.w += p1.w;
        p2.x += p3.x; p2.y += p3.y; p2.z += p3.z; p2.w += p3.w;
        acc.x += p0.x + p2.x; acc.y += p0.y + p2.y;
        acc.z += p0.z + p2.z; acc.w += p0.w + p2.w;
    }
    for (; j < e; ++j) {
        int c = g_dst[j];
        float4 v = *(const float4*)(g_WAT + (size_t)c * HF + lane * 4);
        acc.x += v.x; acc.y += v.y; acc.z += v.z; acc.w += v.w;
    }
    acc.x = rna(acc.x); acc.y = rna(acc.y); acc.z = rna(acc.z); acc.w = rna(acc.w);
    *((float4*)(g_cat + (size_t)w * (2 * HF) + lane * 4)) = acc;
}

// ---------------- tf32 mma.sync GEMM (2-stage) -------------------------------
// RNDA: rna-round A fragments. RNDS: rna-round stores. B pre-rounded.
template<int BN, int EPI, int GUARD, int RNDA, int RNDS>
__global__ __launch_bounds__(256)
void k_mm(const float* __restrict__ A, int lda,
          const float* __restrict__ B,
          const float* __restrict__ bias,
          float* __restrict__ C, int ldc, int K)
{
    constexpr int BM = 128, BK = 16, STR = 20;
    constexpr int WXn = 4, WTN = BN / WXn;
    constexpr int NF = WTN / 8;
    constexpr int MF = 4;
    __shared__ __align__(16) float As[2][BM * STR];
    __shared__ __align__(16) float Bs[2][BN * STR];

    const int tid  = threadIdx.x;
    const int lane = tid & 31, warp = tid >> 5;
    const int wy = warp / WXn, wx = warp % WXn;
    const int g = lane >> 2, tg = lane & 3;
    const int bm = blockIdx.x * BM;

    float acc[MF][NF][4];
    #pragma unroll
    for (int i = 0; i < MF; ++i)
        #pragma unroll
        for (int j = 0; j < NF; ++j)
            #pragma unroll
            for (int c = 0; c < 4; ++c) acc[i][j][c] = 0.f;

    const uint32_t aS = s2u(As), bS = s2u(Bs);
    const int T = K / BK;

    auto load_tiles = [&](int t, int st) {
        const int k0 = t * BK;
        #pragma unroll
        for (int i = 0; i < BM * 4 / 256; ++i) {
            int idx = tid + i * 256;
            int r = idx >> 2, ch = idx & 3;
            uint32_t d = aS + (uint32_t)(st * BM * STR + r * STR + ch * 4) * 4;
            if (GUARD) {
                bool v = (bm + r) < NN;
                cp16z(d, A + (v ? ((size_t)(bm + r) * lda + k0 + ch * 4) : 0), v ? 16 : 0);
            } else {
                cp16(d, A + (size_t)(bm + r) * lda + k0 + ch * 4);
            }
        }
        #pragma unroll
        for (int i = 0; i < BN * 4 / 256; ++i) {
            int idx = tid + i * 256;
            int r = idx >> 2, ch = idx & 3;
            cp16(bS + (uint32_t)(st * BN * STR + r * STR + ch * 4) * 4,
                 B + (size_t)r * K + k0 + ch * 4);
        }
        asm volatile("cp.async.commit_group;");
    };

    load_tiles(0, 0);

    for (int t = 0; t < T; ++t) {
        const int cur = t & 1;
        if (t + 1 < T) {
            load_tiles(t + 1, cur ^ 1);
            asm volatile("cp.async.wait_group 1;");
        } else {
            asm volatile("cp.async.wait_group 0;");
        }
        __syncthreads();

        const float* as = As[cur];
        const float* bs = Bs[cur];
        #pragma unroll
        for (int ks = 0; ks < 2; ++ks) {
            uint32_t af[MF][4], bf[NF][2];
            #pragma unroll
            for (int mf = 0; mf < MF; ++mf) {
                int r0 = (wy * 64 + mf * 16 + g) * STR + ks * 8 + tg;
                if (RNDA) {
                    af[mf][0] = rnau(as[r0]);
                    af[mf][1] = rnau(as[r0 + 8 * STR]);
                    af[mf][2] = rnau(as[r0 + 4]);
                    af[mf][3] = rnau(as[r0 + 8 * STR + 4]);
                } else {
                    af[mf][0] = __float_as_uint(as[r0]);
                    af[mf][1] = __float_as_uint(as[r0 + 8 * STR]);
                    af[mf][2] = __float_as_uint(as[r0 + 4]);
                    af[mf][3] = __float_as_uint(as[r0 + 8 * STR + 4]);
                }
            }
            #pragma unroll
            for (int nf = 0; nf < NF; ++nf) {
                int rb = (wx * WTN + nf * 8 + g) * STR + ks * 8 + tg;
                bf[nf][0] = __float_as_uint(bs[rb]);
                bf[nf][1] = __float_as_uint(bs[rb + 4]);
            }
            #pragma unroll
            for (int mf = 0; mf < MF; ++mf)
                #pragma unroll
                for (int nf = 0; nf < NF; ++nf)
                    MMA_TF32(acc[mf][nf], af[mf], bf[nf]);
        }
        __syncthreads();
    }

    #pragma unroll
    for (int nf = 0; nf < NF; ++nf) {
        int n0 = wx * WTN + nf * 8 + tg * 2;
        float b0 = bias[n0], b1 = bias[n0 + 1];
        #pragma unroll
        for (int mf = 0; mf < MF; ++mf) {
            #pragma unroll
            for (int half = 0; half < 2; ++half) {
                int m = bm + wy * 64 + mf * 16 + g + half * 8;
                if (m >= NN) continue;
                float v0 = acc[mf][nf][half * 2 + 0] + b0;
                float v1 = acc[mf][nf][half * 2 + 1] + b1;
                if (EPI == 2) { v0 = fmaxf(v0, 0.f); v1 = fmaxf(v1, 0.f); }
                if (RNDS) { v0 = rna(v0); v1 = rna(v1); }
                *(float2*)(C + (size_t)m * ldc + n0) = make_float2(v0, v1);
            }
        }
    }
}

// ---------------- fused GEMM2+GEMM3 (dynamic smem) ---------------------------
#define MM23_AS     0
#define MM23_BS     (2 * 128 * 20)
#define MM23_H1     (4 * 128 * 20)
#define MM23_FLOATS (MM23_H1 + 128 * 132)
#define MM23_BYTES  (MM23_FLOATS * 4)

__global__ __launch_bounds__(256)
void k_mm23(const float* __restrict__ bW, const float* __restrict__ bf1)
{
    constexpr int BM = 128, BK = 16, STR = 20, STR2 = 132;
    constexpr int WXn = 4, WTN = 32, NF = 4, MF = 4;
    extern __shared__ float dyn[];
    float* As  = dyn + MM23_AS;
    float* Bs  = dyn + MM23_BS;
    float* h1s = dyn + MM23_H1;
    __shared__ float s_sum[HF], s_sq[HF];

    const int tid  = threadIdx.x;
    const int lane = tid & 31, warp = tid >> 5;
    const int wy = warp / WXn, wx = warp % WXn;
    const int g = lane >> 2, tg = lane & 3;
    const int bm = blockIdx.x * BM;
    const float* cat = g_cat;
    const float* W   = g_Wr;
    const float* Wf1 = g_Wf1r;

    if (tid < HF) { s_sum[tid] = 0.f; s_sq[tid] = 0.f; }

    float acc[MF][NF][4];
    #pragma unroll
    for (int i = 0; i < MF; ++i)
        #pragma unroll
        for (int j = 0; j < NF; ++j)
            #pragma unroll
            for (int c = 0; c < 4; ++c) acc[i][j][c] = 0.f;

    const uint32_t aS = s2u(As), bS = s2u(Bs);

    auto loadB = [&](int t, int st) {
        const int k0 = t * BK;
        #pragma unroll
        for (int i = 0; i < 2; ++i) {
            int idx = tid + i * 256;
            int r = idx >> 2, ch = idx & 3;
            cp16(aS + (uint32_t)(st * BM * STR + r * STR + ch * 4) * 4,
                 cat + (size_t)(bm + r) * 256 + k0 + ch * 4);
        }
        #pragma unroll
        for (int i = 0; i < 2; ++i) {
            int idx = tid + i * 256;
            int r = idx >> 2, ch = idx & 3;
            cp16(bS + (uint32_t)(st * HF * STR + r * STR + ch * 4) * 4,
                 W + (size_t)r * 256 + k0 + ch * 4);
        }
        asm volatile("cp.async.commit_group;");
    };

    loadB(0, 0);
    for (int t = 0; t < 16; ++t) {
        const int cur = t & 1;
        if (t + 1 < 16) {
            loadB(t + 1, cur ^ 1);
            asm volatile("cp.async.wait_group 1;");
        } else {
            asm volatile("cp.async.wait_group 0;");
        }
        __syncthreads();
        const float* as = As + cur * BM * STR;
        const float* bs = Bs + cur * HF * STR;
        #pragma unroll
        for (int ks = 0; ks < 2; ++ks) {
            uint32_t af[MF][4], bf[NF][2];
            #pragma unroll
            for (int mf = 0; mf < MF; ++mf) {
                int r0 = (wy * 64 + mf * 16 + g) * STR + ks * 8 + tg;
                af[mf][0] = __float_as_uint(as[r0]);
                af[mf][1] = __float_as_uint(as[r0 + 8 * STR]);
                af[mf][2] = __float_as_uint(as[r0 + 4]);
                af[mf][3] = __float_as_uint(as[r0 + 8 * STR + 4]);
            }
            #pragma unroll
            for (int nf = 0; nf < NF; ++nf) {
                int rb = (wx * WTN + nf * 8 + g) * STR + ks * 8 + tg;
                bf[nf][0] = __float_as_uint(bs[rb]);
                bf[nf][1] = __float_as_uint(bs[rb + 4]);
            }
            #pragma unroll
            for (int mf = 0; mf < MF; ++mf)
                #pragma unroll
                for (int nf = 0; nf < NF; ++nf)
                    MMA_TF32(acc[mf][nf], af[mf], bf[nf]);
        }
        __syncthreads();
    }

    // prefetch stage-C B tile 0 (Wf1)
    {
        #pragma unroll
        for (int i = 0; i < 2; ++i) {
            int idx = tid + i * 256;
            int r = idx >> 2, ch = idx & 3;
            cp16(bS + (uint32_t)(r * STR + ch * 4) * 4,
                 Wf1 + (size_t)r * HF + ch * 4);
        }
        asm volatile("cp.async.commit_group;");
    }

    // stage-B epilogue: skip + relu + rna -> h1s
    #pragma unroll
    for (int nf = 0; nf < NF; ++nf) {
        int n0 = wx * WTN + nf * 8 + tg * 2;
        float b0 = bW[n0], b1 = bW[n0 + 1];
        #pragma unroll
        for (int mf = 0; mf < MF; ++mf) {
            #pragma unroll
            for (int half = 0; half < 2; ++half) {
                int ml = wy * 64 + mf * 16 + g + half * 8;
                const float* sp = cat + (size_t)(bm + ml) * 256;
                float v0 = acc[mf][nf][half * 2 + 0] + b0 + sp[n0]     + sp[128 + n0];
                float v1 = acc[mf][nf][half * 2 + 1] + b1 + sp[n0 + 1] + sp[128 + n0 + 1];
                v0 = rna(fmaxf(v0, 0.f)); v1 = rna(fmaxf(v1, 0.f));
                *(float2*)(h1s + ml * STR2 + n0) = make_float2(v0, v1);
                acc[mf][nf][half * 2 + 0] = 0.f;
                acc[mf][nf][half * 2 + 1] = 0.f;
            }
        }
    }
    __syncthreads();

    // stage C: K = 128, A from h1s, B = Wf1
    auto loadC = [&](int t, int st) {
        const int k0 = t * BK;
        #pragma unroll
        for (int i = 0; i < 2; ++i) {
            int idx = tid + i * 256;
            int r = idx >> 2, ch = idx & 3;
            cp16(bS + (uint32_t)(st * HF * STR + r * STR + ch * 4) * 4,
                 Wf1 + (size_t)r * HF + k0 + ch * 4);
        }
        asm volatile("cp.async.commit_group;");
    };

    for (int t = 0; t < 8; ++t) {
        const int cur = t & 1;
        if (t + 1 < 8) {
            loadC(t + 1, cur ^ 1);
            asm volatile("cp.async.wait_group 1;");
        } else {
            asm volatile("cp.async.wait_group 0;");
        }
        __syncthreads();
        const float* bs = Bs + cur * HF * STR;
        const int kb = t * BK;
        #pragma unroll
        for (int ks = 0; ks < 2; ++ks) {
            uint32_t af[MF][4], bf[NF][2];
            #pragma unroll
            for (int mf = 0; mf < MF; ++mf) {
                int r0 = (wy * 64 + mf * 16 + g) * STR2 + kb + ks * 8 + tg;
                af[mf][0] = __float_as_uint(h1s[r0]);
                af[mf][1] = __float_as_uint(h1s[r0 + 8 * STR2]);
                af[mf][2] = __float_as_uint(h1s[r0 + 4]);
                af[mf][3] = __float_as_uint(h1s[r0 + 8 * STR2 + 4]);
            }
            #pragma unroll
            for (int nf = 0; nf < NF; ++nf) {
                int rb = (wx * WTN + nf * 8 + g) * STR + ks * 8 + tg;
                bf[nf][0] = __float_as_uint(bs[rb]);
                bf[nf][1] = __float_as_uint(bs[rb + 4]);
            }
            #pragma unroll
            for (int mf = 0; mf < MF; ++mf)
                #pragma unroll
                for (int nf = 0; nf < NF; ++nf)
                    MMA_TF32(acc[mf][nf], af[mf], bf[nf]);
        }
        __syncthreads();
    }

    // stage-C epilogue: relu; stats on unrounded; store rounded g_t
    #pragma unroll
    for (int nf = 0; nf < NF; ++nf) {
        int n0 = wx * WTN + nf * 8 + tg * 2;
        float b0 = bf1[n0], b1 = bf1[n0 + 1];
        float ps0 = 0.f, pq0 = 0.f, ps1 = 0.f, pq1 = 0.f;
        #pragma unroll
        for (int mf = 0; mf < MF; ++mf) {
            #pragma unroll
            for (int half = 0; half < 2; ++half) {
                int m = bm + wy * 64 + mf * 16 + g + half * 8;
                if (m >= NN) continue;
                float v0 = fmaxf(acc[mf][nf][half * 2 + 0] + b0, 0.f);
                float v1 = fmaxf(acc[mf][nf][half * 2 + 1] + b1, 0.f);
                ps0 += v0; pq0 += v0 * v0; ps1 += v1; pq1 += v1 * v1;
                *(float2*)(g_t + (size_t)m * HF + n0) = make_float2(rna(v0), rna(v1));
            }
        }
        #pragma unroll
        for (int msk = 16; msk >= 4; msk >>= 1) {
            ps0 += __shfl_xor_sync(0xffffffffu, ps0, msk);
            pq0 += __shfl_xor_sync(0xffffffffu, pq0, msk);
            ps1 += __shfl_xor_sync(0xffffffffu, ps1, msk);
            pq1 += __shfl_xor_sync(0xffffffffu, pq1, msk);
        }
        if (g == 0) {
            atomicAdd(&s_sum[n0],     ps0); atomicAdd(&s_sq[n0],     pq0);
            atomicAdd(&s_sum[n0 + 1], ps1); atomicAdd(&s_sq[n0 + 1], pq1);
        }
    }
    __syncthreads();
    if (tid < HF) {
        atomicAdd(&g_sum[tid],   s_sum[tid]);
        atomicAdd(&g_sumsq[tid], s_sq[tid]);
    }
}

// ---------------- fold BN into Wf2/bf2; self-clean stats + rmin --------------
__global__ void k_fold(const float* __restrict__ gamma, const float* __restrict__ beta,
                       const float* __restrict__ Wf2,   const float* __restrict__ bf2,
                       int M) {
    __shared__ float a[HF], b[HF];
    int t = threadIdx.x;
    if (t < HF) {
        float inv  = 1.f / (float)M;
        float mean = g_sum[t] * inv;
        float var  = g_sumsq[t] * inv - mean * mean;
        float av   = gamma[t] * rsqrtf(var + 1e-5f);
        a[t] = av;
        b[t] = beta[t] - mean * av;
        g_sum[t] = 0.f;                         // self-clean for next replay
        g_sumsq[t] = 0.f;
    }
    if (t == 0) g_rmin = 0x7fffffff;            // self-clean
    __syncthreads();
    for (int i = t; i < OF * HF; i += blockDim.x)
        g_Wf2p[i] = rna(Wf2[i] * a[i & (HF - 1)]);
    if (t < OF) {
        float s = bf2[t];
        for (int h = 0; h < HF; ++h) s += b[h] * Wf2[t * HF + h];
        g_bf2p[t] = s;
    }
}

// -----------------------------------------------------------------------------
extern "C" void kernel_launch(void* const* d_in, const int* in_sizes, int n_in,
                              void* d_out, int out_size) {
    const float* x     = (const float*)d_in[0];
    const int*   ei    = (const int*)  d_in[1];
    const float* WA    = (const float*)d_in[2];
    const float* bA    = (const float*)d_in[3];
    const float* WX    = (const float*)d_in[4];
    const float* bX    = (const float*)d_in[5];
    const float* W     = (const float*)d_in[6];
    const float* bW    = (const float*)d_in[7];
    const float* Wf1   = (const float*)d_in[8];
    const float* bf1   = (const float*)d_in[9];
    const float* gamma = (const float*)d_in[10];
    const float* beta  = (const float*)d_in[11];
    const float* Wf2   = (const float*)d_in[12];
    const float* bf2   = (const float*)d_in[13];
    float* out = (float*)d_out;

    const int E = in_sizes[1] / 2;
    const int M = NN;
    const int* row = ei;
    const int* col = ei + E;

    float *pCat, *pT, *pWXr, *pW2, *pB2;
    cudaGetSymbolAddress((void**)&pCat, g_cat);
    cudaGetSymbolAddress((void**)&pT,   g_t);
    cudaGetSymbolAddress((void**)&pWXr, g_WXr);
    cudaGetSymbolAddress((void**)&pW2,  g_Wf2p);
    cudaGetSymbolAddress((void**)&pB2,  g_bf2p);

    static int inited = 0;
    static cudaStream_t sT, sG;
    static cudaEvent_t evRoot, evT, evG;
    if (!inited) {
        cudaFuncSetAttribute(k_mm23, cudaFuncAttributeMaxDynamicSharedMemorySize,
                             MM23_BYTES);
        cudaStreamCreateWithFlags(&sT, cudaStreamNonBlocking);
        cudaStreamCreateWithFlags(&sG, cudaStreamNonBlocking);
        cudaEventCreateWithFlags(&evRoot, cudaEventDisableTiming);
        cudaEventCreateWithFlags(&evT,    cudaEventDisableTiming);
        cudaEventCreateWithFlags(&evG,    cudaEventDisableTiming);
        inited = 1;
    }

    // ---- fork -----------------------------------------------------------------
    cudaEventRecord(evRoot, 0);
    cudaStreamWaitEvent(sT, evRoot, 0);
    cudaStreamWaitEvent(sG, evRoot, 0);

    // stream sT: transpose WA
    k_transpose<<<dim3((NN + 31) / 32, HF / 32), dim3(32, 8), 0, sT>>>(WA);
    cudaEventRecord(evT, sT);

    // stream sG: round weights, then GEMM1 (unified, full grid)
    k_roundw<<<(HF * INF + 255) / 256, 256, 0, sG>>>(WX, W, Wf1);
    k_mm<128, 0, 1, 1, 1><<<GBLK, 256, 0, sG>>>(x, INF, pWXr, bX, pCat + HF, 2 * HF, INF);
    cudaEventRecord(evG, sG);

    // stream 0: edge pipeline (no k_init — state is self-cleaning)
    k_hist<<<(E / 8 + 255) / 256, 256>>>(row, E);
    k_scanA<<<SCB, 256>>>();
    k_scanB<<<1, 256>>>();
    k_scanC<<<SCB, 256>>>(E);
    k_bin<<<(E / 8 + 255) / 256, 256>>>(row, col, E);

    // join transpose, then gather (unified)
    cudaStreamWaitEvent(0, evT, 0);
    k_gather<<<(NN * 32 + 255) / 256, 256>>>(bA);

    // join GEMM1, then fused GEMM2+3 (unified)
    cudaStreamWaitEvent(0, evG, 0);
    k_mm23<<<GBLK, 256, MM23_BYTES>>>(bW, bf1);

    // fold BN, final GEMM
    k_fold<<<1, 256>>>(gamma, beta, Wf2, bf2, M);
    k_mm<64, 0, 0, 0, 0><<<GBLK, 256>>>(pT, HF, pW2, pB2, out, OF, HF);
}